// round 15
// baseline (speedup 1.0000x reference)
#include <cuda_runtime.h>
#include <math.h>
#include <stdint.h>

// Problem constants (GAT: N=50000 nodes, E=800000 edges, F_in=512, H=4, C=64, OUT=40)
#define F_IN   512
#define HC     256      // H*C for layer 1
#define NH     4
#define OUTC   40
#define MAXN   50000
#define MAXE   800000
#define MAXEDG (MAXE + MAXN)   // + self loops

#define NEG_INF __int_as_float(0xff800000u)

// ---------------- scratch (static device globals; no allocation allowed) ----
__device__ __align__(16) float g_h1[(size_t)MAXN * HC];   // x@W1
__device__ __align__(16) float g_h2[(size_t)MAXN * HC];   // layer1 output (post elu)
__device__ __align__(16) float g_h3[(size_t)MAXN * OUTC]; // h2@W2
__device__ float g_asrc1[MAXN * NH];
__device__ float g_adst1[MAXN * NH];
__device__ float g_asrc2[MAXN];
__device__ float g_adst2[MAXN];
__device__ int   g_deg[MAXN];
__device__ int   g_rowptr[MAXN + 1];
__device__ int   g_cursor[MAXN];
__device__ int   g_esrc[MAXEDG];
__device__ int   g_src32[MAXE];
__device__ int   g_dst32[MAXE];
__device__ int   g_is64;
// W1 pre-split to bf16 hi/lo, transposed to [n][k]; reinterpreted as packed
// bf16x2 words (word w = k-pair {2w, 2w+1}) for the MMA B operand.
__device__ __align__(16) unsigned short g_w1hi[(size_t)HC * F_IN];
__device__ __align__(16) unsigned short g_w1lo[(size_t)HC * F_IN];

// ---------------- edge dtype detection ------------------------------------
__global__ void k_detect(const void* __restrict__ ei, int E, int N) {
    if (blockIdx.x == 0 && threadIdx.x == 0) {
        const long long* p = (const long long*)ei;
        int ok64 = 1;
        int n = E < 64 ? E : 64;
        for (int i = 0; i < n; i++) {
            long long v = p[i];
            if (v < 0 || v >= (long long)N) { ok64 = 0; break; }
        }
        g_is64 = ok64;
    }
}

__global__ void k_init_deg(int n) {
    int i = blockIdx.x * blockDim.x + threadIdx.x;
    if (i < n) g_deg[i] = 1;   // self loop
}

// fused: dtype-normalize edges AND count in-degrees in one pass
__global__ void k_convert_count(const void* __restrict__ ei, int E, int N) {
    int i = blockIdx.x * blockDim.x + threadIdx.x;
    if (i >= E) return;
    int s, d;
    if (g_is64) {
        const long long* p = (const long long*)ei;
        s = (int)p[i];
        d = (int)p[E + i];
    } else {
        const int* p = (const int*)ei;
        s = p[i];
        d = p[E + i];
    }
    s = s < 0 ? 0 : (s >= N ? N - 1 : s);
    d = d < 0 ? 0 : (d >= N ? N - 1 : d);
    g_src32[i] = s;
    g_dst32[i] = d;
    atomicAdd(&g_deg[d], 1);
}

// single-block exclusive scan of g_deg -> g_rowptr, fused self-loop + cursor
__global__ void k_scan(int n) {
    __shared__ int s[1024];
    int t = threadIdx.x;
    int chunk = (n + 1023) >> 10;
    int b = t * chunk;
    int e = min(b + chunk, n);
    int sum = 0;
    for (int i = b; i < e; i++) sum += g_deg[i];
    s[t] = sum;
    __syncthreads();
    for (int off = 1; off < 1024; off <<= 1) {
        int v = (t >= off) ? s[t - off] : 0;
        __syncthreads();
        s[t] += v;
        __syncthreads();
    }
    int run = (t == 0) ? 0 : s[t - 1];
    for (int i = b; i < e; i++) {
        g_rowptr[i] = run;
        g_esrc[run] = i;            // self loop placed first
        g_cursor[i] = run + 1;
        run += g_deg[i];
    }
    if (t == 1023) g_rowptr[n] = s[1023];
}

__global__ void k_scatter(int E) {
    int i = blockIdx.x * blockDim.x + threadIdx.x;
    if (i < E) {
        int d = g_dst32[i];
        int p = atomicAdd(&g_cursor[d], 1);
        g_esrc[p] = g_src32[i];
    }
}

// ---------------- W1 pre-split: fp32 [k][n] -> bf16 hi/lo [n][k] ------------
__global__ void k_prepw(const float* __restrict__ W1) {
    int i = blockIdx.x * blockDim.x + threadIdx.x;
    if (i >= F_IN * HC) return;
    int k = i >> 8;        // row in W1 (k index), HC=256
    int n = i & 255;       // col in W1 (output channel)
    float v = W1[i];
    unsigned short hb, lb;
    asm("cvt.rn.bf16.f32 %0, %1;" : "=h"(hb) : "f"(v));
    float r = v - __uint_as_float((uint32_t)hb << 16);
    asm("cvt.rn.bf16.f32 %0, %1;" : "=h"(lb) : "f"(r));
    g_w1hi[(size_t)n * F_IN + k] = hb;
    g_w1lo[(size_t)n * F_IN + k] = lb;
}

// ---------------- GEMM1: legacy mma.sync bf16 m16n8k16, 3-term split --------
// h1[M x 256] = x[M x 512] @ W1[512 x 256]; ah*bh + ah*bl + al*bh.
// Software-pipelined: next tile's global loads prefetched during MMA compute.
__device__ __forceinline__ void mma16(float4& c, unsigned a0, unsigned a1,
                                      unsigned a2, unsigned a3,
                                      unsigned b0, unsigned b1) {
    asm volatile(
        "mma.sync.aligned.m16n8k16.row.col.f32.bf16.bf16.f32 "
        "{%0,%1,%2,%3}, {%4,%5,%6,%7}, {%8,%9}, {%0,%1,%2,%3};"
        : "+f"(c.x), "+f"(c.y), "+f"(c.z), "+f"(c.w)
        : "r"(a0), "r"(a1), "r"(a2), "r"(a3), "r"(b0), "r"(b1));
}

#define PITCH 136   // smem pitch in words: fragment gathers conflict-free

__global__ __launch_bounds__(256) void k_gemm1_bf(const float* __restrict__ A, int M) {
    // packed bf16x2 tiles, word index kw = k-pair, kw in [0,8)
    __shared__ unsigned As2h[8][PITCH];
    __shared__ unsigned As2l[8][PITCH];
    __shared__ unsigned Bs2h[8][PITCH];
    __shared__ unsigned Bs2l[8][PITCH];

    int t    = threadIdx.x;
    int warp = t >> 5, lane = t & 31;
    int wm   = (warp >> 2) * 64;     // warp M offset (2 warps in M)
    int wn   = (warp & 3) * 32;      // warp N offset (4 warps in N)
    int gq   = lane >> 2;            // group id 0..7
    int tq   = lane & 3;             // thread-in-group 0..3
    int bm   = blockIdx.x * 128;
    int bn   = blockIdx.y * 128;

    const unsigned* w1h = (const unsigned*)g_w1hi;   // [n][256] packed words
    const unsigned* w1l = (const unsigned*)g_w1lo;

    // per-thread load coordinates (A: 2 float4 / iter, B: 2 uint2-pairs / iter)
    int a_row[2], a_c4[2];
    const float* a_ptr[2];
    int b_kw[2];
    const unsigned* bh_ptr[2];
    const unsigned* bl_ptr[2];
#pragma unroll
    for (int i = 0; i < 2; i++) {
        int idx = t + i * 256;
        a_row[i] = idx >> 2;
        a_c4[i]  = (idx & 3) * 4;
        int gr = bm + a_row[i];
        a_ptr[i] = (gr < M) ? (A + (size_t)gr * F_IN + a_c4[i]) : 0;
        int e = t + i * 256;
        int col = e >> 2;
        b_kw[i] = (e & 3) * 2;
        size_t gi = (size_t)(bn + col) * 256 + b_kw[i];
        bh_ptr[i] = w1h + gi;
        bl_ptr[i] = w1l + gi;
    }

    float4 acc[4][4];
#pragma unroll
    for (int i = 0; i < 4; i++)
#pragma unroll
        for (int j = 0; j < 4; j++) acc[i][j] = make_float4(0.f, 0.f, 0.f, 0.f);

    // prologue: load tile kt=0
    float4 pa[2];
    uint2  pbh[2], pbl[2];
#pragma unroll
    for (int i = 0; i < 2; i++) {
        pa[i] = a_ptr[i] ? *(const float4*)(a_ptr[i]) : make_float4(0.f, 0.f, 0.f, 0.f);
        pbh[i] = *(const uint2*)(bh_ptr[i]);
        pbl[i] = *(const uint2*)(bl_ptr[i]);
    }

    for (int kt = 0; kt < F_IN; kt += 16) {
        // store current prefetched tile to smem (convert A on the fly)
#pragma unroll
        for (int i = 0; i < 2; i++) {
            int idx = t + i * 256;
            int row = a_row[i];
            int kw  = (idx & 3) * 2;
            float4 v = pa[i];
            unsigned ph01, ph23, pl01, pl23;
            asm("cvt.rn.bf16x2.f32 %0, %1, %2;" : "=r"(ph01) : "f"(v.y), "f"(v.x));
            asm("cvt.rn.bf16x2.f32 %0, %1, %2;" : "=r"(ph23) : "f"(v.w), "f"(v.z));
            float r0 = v.x - __uint_as_float(ph01 << 16);
            float r1 = v.y - __uint_as_float(ph01 & 0xffff0000u);
            float r2 = v.z - __uint_as_float(ph23 << 16);
            float r3 = v.w - __uint_as_float(ph23 & 0xffff0000u);
            asm("cvt.rn.bf16x2.f32 %0, %1, %2;" : "=r"(pl01) : "f"(r1), "f"(r0));
            asm("cvt.rn.bf16x2.f32 %0, %1, %2;" : "=r"(pl23) : "f"(r3), "f"(r2));
            As2h[kw][row]     = ph01;
            As2h[kw + 1][row] = ph23;
            As2l[kw][row]     = pl01;
            As2l[kw + 1][row] = pl23;
            int e = t + i * 256;
            int col = e >> 2;
            int kw2 = b_kw[i];
            Bs2h[kw2][col]     = pbh[i].x;
            Bs2h[kw2 + 1][col] = pbh[i].y;
            Bs2l[kw2][col]     = pbl[i].x;
            Bs2l[kw2 + 1][col] = pbl[i].y;
        }
        __syncthreads();

        // prefetch next tile's globals (in flight during the MMAs below)
        if (kt + 16 < F_IN) {
            int koff = kt + 16;
#pragma unroll
            for (int i = 0; i < 2; i++) {
                pa[i] = a_ptr[i] ? *(const float4*)(a_ptr[i] + koff)
                                 : make_float4(0.f, 0.f, 0.f, 0.f);
                pbh[i] = *(const uint2*)(bh_ptr[i] + (koff >> 1));
                pbl[i] = *(const uint2*)(bl_ptr[i] + (koff >> 1));
            }
        }

        unsigned ah[4][4], al[4][4], bh[4][2], bl[4][2];
#pragma unroll
        for (int mi = 0; mi < 4; mi++) {
            int m = wm + mi * 16 + gq;
            ah[mi][0] = As2h[tq][m];
            ah[mi][1] = As2h[tq][m + 8];
            ah[mi][2] = As2h[tq + 4][m];
            ah[mi][3] = As2h[tq + 4][m + 8];
            al[mi][0] = As2l[tq][m];
            al[mi][1] = As2l[tq][m + 8];
            al[mi][2] = As2l[tq + 4][m];
            al[mi][3] = As2l[tq + 4][m + 8];
        }
#pragma unroll
        for (int nj = 0; nj < 4; nj++) {
            int n = wn + nj * 8 + gq;
            bh[nj][0] = Bs2h[tq][n];
            bh[nj][1] = Bs2h[tq + 4][n];
            bl[nj][0] = Bs2l[tq][n];
            bl[nj][1] = Bs2l[tq + 4][n];
        }
#pragma unroll
        for (int mi = 0; mi < 4; mi++)
#pragma unroll
            for (int nj = 0; nj < 4; nj++) {
                mma16(acc[mi][nj], ah[mi][0], ah[mi][1], ah[mi][2], ah[mi][3],
                      bl[nj][0], bl[nj][1]);                    // hi*lo
                mma16(acc[mi][nj], al[mi][0], al[mi][1], al[mi][2], al[mi][3],
                      bh[nj][0], bh[nj][1]);                    // lo*hi
                mma16(acc[mi][nj], ah[mi][0], ah[mi][1], ah[mi][2], ah[mi][3],
                      bh[nj][0], bh[nj][1]);                    // hi*hi
            }
        __syncthreads();
    }

    // epilogue: c0,c1 (row g, cols 2tq,2tq+1), c2,c3 (row g+8)
#pragma unroll
    for (int mi = 0; mi < 4; mi++) {
        int row0 = bm + wm + mi * 16 + gq;
        int row1 = row0 + 8;
#pragma unroll
        for (int nj = 0; nj < 4; nj++) {
            int col = bn + wn + nj * 8 + tq * 2;
            if (row0 < M)
                *(float2*)(g_h1 + (size_t)row0 * HC + col) =
                    make_float2(acc[mi][nj].x, acc[mi][nj].y);
            if (row1 < M)
                *(float2*)(g_h1 + (size_t)row1 * HC + col) =
                    make_float2(acc[mi][nj].z, acc[mi][nj].w);
        }
    }
}

// ---------------- attention coefficients layer 1 ---------------------------
__global__ void k_attn1(const float* __restrict__ att_src,
                        const float* __restrict__ att_dst, int N) {
    int warp = (blockIdx.x * blockDim.x + threadIdx.x) >> 5;
    int lane = threadIdx.x & 31;
    if (warp >= N) return;
    const float4* hp = (const float4*)(g_h1 + (size_t)warp * HC);
    float4 h0 = hp[lane * 2], h1v = hp[lane * 2 + 1];
    int base = lane * 8;
    float4 s0 = *(const float4*)(att_src + base);
    float4 s1 = *(const float4*)(att_src + base + 4);
    float4 d0 = *(const float4*)(att_dst + base);
    float4 d1 = *(const float4*)(att_dst + base + 4);
    float ps = h0.x * s0.x + h0.y * s0.y + h0.z * s0.z + h0.w * s0.w
             + h1v.x * s1.x + h1v.y * s1.y + h1v.z * s1.z + h1v.w * s1.w;
    float pd = h0.x * d0.x + h0.y * d0.y + h0.z * d0.z + h0.w * d0.w
             + h1v.x * d1.x + h1v.y * d1.y + h1v.z * d1.z + h1v.w * d1.w;
#pragma unroll
    for (int o = 4; o; o >>= 1) {
        ps += __shfl_xor_sync(0xffffffffu, ps, o);
        pd += __shfl_xor_sync(0xffffffffu, pd, o);
    }
    if ((lane & 7) == 0) {
        int h = lane >> 3;
        g_asrc1[warp * NH + h] = ps;
        g_adst1[warp * NH + h] = pd;
    }
}

// ---------------- layer-1 aggregation: warp/node, online softmax -----------
__global__ void k_agg1(const float* __restrict__ b1, int N) {
    int node = (blockIdx.x * blockDim.x + threadIdx.x) >> 5;
    int lane = threadIdx.x & 31;
    if (node >= N) return;
    int head = lane >> 3;
    int start = g_rowptr[node], end = g_rowptr[node + 1];
    float ad = g_adst1[node * NH + head];
    float m = NEG_INF, d = 0.f;
    float acc[8];
#pragma unroll
    for (int j = 0; j < 8; j++) acc[j] = 0.f;

    for (int e = start; e < end; e++) {
        int s = g_esrc[e];
        float al = g_asrc1[s * NH + head] + ad;
        al = al > 0.f ? al : 0.2f * al;             // leaky_relu
        float mn = fmaxf(m, al);
        float sc = __expf(m - mn);                  // 0 on first edge
        float w  = __expf(al - mn);
        d = d * sc + w;
        const float4* hp = (const float4*)(g_h1 + (size_t)s * HC) + lane * 2;
        float4 v0 = hp[0], v1 = hp[1];
        acc[0] = acc[0] * sc + w * v0.x;
        acc[1] = acc[1] * sc + w * v0.y;
        acc[2] = acc[2] * sc + w * v0.z;
        acc[3] = acc[3] * sc + w * v0.w;
        acc[4] = acc[4] * sc + w * v1.x;
        acc[5] = acc[5] * sc + w * v1.y;
        acc[6] = acc[6] * sc + w * v1.z;
        acc[7] = acc[7] * sc + w * v1.w;
        m = mn;
    }
    float inv = 1.f / (d + 1e-16f);
    int col = lane * 8;
#pragma unroll
    for (int j = 0; j < 8; j++) {
        float v = acc[j] * inv + __ldg(b1 + col + j);
        acc[j] = v > 0.f ? v : (expf(v) - 1.f);     // elu
    }
    float4* op = (float4*)(g_h2 + (size_t)node * HC + col);
    op[0] = make_float4(acc[0], acc[1], acc[2], acc[3]);
    op[1] = make_float4(acc[4], acc[5], acc[6], acc[7]);
}

// ---------------- GEMM2: h3[M x 40] = h2[M x 256] @ W2[256 x 40] -----------
__global__ __launch_bounds__(256) void k_gemm2(const float* __restrict__ W2, int M) {
    __shared__ float hs[64][65];
    __shared__ float ws[64][OUTC];
    int t = threadIdx.x;
    int bm = blockIdx.x * 64;
    int cg = t & 7;
    int rg = t >> 3;
    float acc[2][5];
#pragma unroll
    for (int r = 0; r < 2; r++)
#pragma unroll
        for (int j = 0; j < 5; j++) acc[r][j] = 0.f;

    for (int kt = 0; kt < HC; kt += 64) {
#pragma unroll
        for (int i = 0; i < 4; i++) {
            int idx = t + i * 256;
            int row = idx >> 4;
            int c4  = (idx & 15) * 4;
            float4 v = make_float4(0.f, 0.f, 0.f, 0.f);
            int gr = bm + row;
            if (gr < M) v = *(const float4*)(g_h2 + (size_t)gr * HC + kt + c4);
            hs[row][c4 + 0] = v.x;
            hs[row][c4 + 1] = v.y;
            hs[row][c4 + 2] = v.z;
            hs[row][c4 + 3] = v.w;
        }
#pragma unroll
        for (int i = 0; i < 10; i++) {
            int idx = t + i * 256;
            int kr = idx / OUTC;
            int c  = idx - kr * OUTC;
            ws[kr][c] = W2[(size_t)(kt + kr) * OUTC + c];
        }
        __syncthreads();
#pragma unroll
        for (int k = 0; k < 64; k++) {
            float h0 = hs[rg * 2][k];
            float h1v = hs[rg * 2 + 1][k];
#pragma unroll
            for (int j = 0; j < 5; j++) {
                float w = ws[k][cg * 5 + j];
                acc[0][j] += h0 * w;
                acc[1][j] += h1v * w;
            }
        }
        __syncthreads();
    }
#pragma unroll
    for (int r = 0; r < 2; r++) {
        int gr = bm + rg * 2 + r;
        if (gr >= M) continue;
#pragma unroll
        for (int j = 0; j < 5; j++)
            g_h3[(size_t)gr * OUTC + cg * 5 + j] = acc[r][j];
    }
}

// ---------------- attention coefficients layer 2 ---------------------------
__global__ void k_attn2(const float* __restrict__ att_src,
                        const float* __restrict__ att_dst, int N) {
    int node = (blockIdx.x * blockDim.x + threadIdx.x) >> 5;
    int lane = threadIdx.x & 31;
    if (node >= N) return;
    const float* hp = g_h3 + (size_t)node * OUTC;
    float ps = hp[lane] * __ldg(att_src + lane);
    float pd = hp[lane] * __ldg(att_dst + lane);
    if (lane < 8) {
        ps += hp[32 + lane] * __ldg(att_src + 32 + lane);
        pd += hp[32 + lane] * __ldg(att_dst + 32 + lane);
    }
#pragma unroll
    for (int o = 16; o; o >>= 1) {
        ps += __shfl_xor_sync(0xffffffffu, ps, o);
        pd += __shfl_xor_sync(0xffffffffu, pd, o);
    }
    if (lane == 0) { g_asrc2[node] = ps; g_adst2[node] = pd; }
}

// ---------------- layer-2 aggregation + bias + log_softmax -----------------
__global__ void k_agg2(const float* __restrict__ b2, float* __restrict__ out, int N) {
    int node = (blockIdx.x * blockDim.x + threadIdx.x) >> 5;
    int lane = threadIdx.x & 31;
    if (node >= N) return;
    int start = g_rowptr[node], end = g_rowptr[node + 1];
    float ad = g_adst2[node];
    float m = NEG_INF, d = 0.f;
    float a0 = 0.f, a1 = 0.f;
    for (int e = start; e < end; e++) {
        int s = g_esrc[e];
        float al = g_asrc2[s] + ad;
        al = al > 0.f ? al : 0.2f * al;
        float mn = fmaxf(m, al);
        float sc = __expf(m - mn);
        float w  = __expf(al - mn);
        d = d * sc + w;
        const float* hp = g_h3 + (size_t)s * OUTC;
        float v0 = hp[lane];
        float v1 = (lane < 8) ? hp[32 + lane] : 0.f;
        a0 = a0 * sc + w * v0;
        a1 = a1 * sc + w * v1;
        m = mn;
    }
    float inv = 1.f / (d + 1e-16f);
    float o0 = a0 * inv + __ldg(b2 + lane);
    float o1 = (lane < 8) ? (a1 * inv + __ldg(b2 + 32 + lane)) : NEG_INF;
    float mx = fmaxf(o0, o1);
#pragma unroll
    for (int o = 16; o; o >>= 1) mx = fmaxf(mx, __shfl_xor_sync(0xffffffffu, mx, o));
    float se = expf(o0 - mx) + ((lane < 8) ? expf(o1 - mx) : 0.f);
#pragma unroll
    for (int o = 16; o; o >>= 1) se += __shfl_xor_sync(0xffffffffu, se, o);
    float L = logf(se);
    float* op = out + (size_t)node * OUTC;
    op[lane] = o0 - mx - L;
    if (lane < 8) op[32 + lane] = o1 - mx - L;
}

// ---------------- launch ----------------------------------------------------
extern "C" void kernel_launch(void* const* d_in, const int* in_sizes, int n_in,
                              void* d_out, int out_size) {
    const float* x   = (const float*)d_in[0];
    const void*  ei  = d_in[1];
    const float* W1  = (const float*)d_in[2];
    const float* as1 = (const float*)d_in[3];
    const float* ad1 = (const float*)d_in[4];
    const float* b1  = (const float*)d_in[5];
    const float* W2  = (const float*)d_in[6];
    const float* as2 = (const float*)d_in[7];
    const float* ad2 = (const float*)d_in[8];
    const float* b2  = (const float*)d_in[9];
    float*       out = (float*)d_out;

    int N = in_sizes[0] / F_IN;
    int E = in_sizes[1] / 2;

    int nb = (N + 255) / 256;
    int eb = (E + 255) / 256;
    int wb = (N + 7) / 8;   // one warp per node, 8 warps per block

    // Edge dtype normalization + CSR by destination (self loops included)
    k_detect<<<1, 32>>>(ei, E, N);
    k_init_deg<<<nb, 256>>>(N);
    k_convert_count<<<eb, 256>>>(ei, E, N);
    k_scan<<<1, 1024>>>(N);
    k_scatter<<<eb, 256>>>(E);

    // Layer 1
    k_prepw<<<(F_IN * HC + 255) / 256, 256>>>(W1);
    dim3 g1((N + 127) / 128, HC / 128);
    k_gemm1_bf<<<g1, 256>>>(x, N);
    k_attn1<<<wb, 256>>>(as1, ad1, N);
    k_agg1<<<wb, 256>>>(b1, N);

    // Layer 2
    k_gemm2<<<(N + 63) / 64, 256>>>(W2, N);
    k_attn2<<<wb, 256>>>(as2, ad2, N);
    k_agg2<<<wb, 256>>>(b2, out, N);
}

// round 16
// speedup vs baseline: 1.1285x; 1.1285x over previous
#include <cuda_runtime.h>
#include <math.h>
#include <stdint.h>

// Problem constants (GAT: N=50000 nodes, E=800000 edges, F_in=512, H=4, C=64, OUT=40)
#define F_IN   512
#define HC     256      // H*C for layer 1
#define NH     4
#define OUTC   40
#define MAXN   50000
#define MAXE   800000
#define MAXEDG (MAXE + MAXN)   // + self loops

#define NEG_INF __int_as_float(0xff800000u)

// ---------------- scratch (static device globals; no allocation allowed) ----
__device__ __align__(16) float g_h1[(size_t)MAXN * HC];   // x@W1
__device__ __align__(16) float g_h2[(size_t)MAXN * HC];   // layer1 output (post elu)
__device__ __align__(16) float g_h3[(size_t)MAXN * OUTC]; // h2@W2
__device__ float g_asrc1[MAXN * NH];
__device__ float g_adst1[MAXN * NH];
__device__ float g_asrc2[MAXN];
__device__ float g_adst2[MAXN];
__device__ int   g_deg[MAXN];
__device__ int   g_rowptr[MAXN + 1];
__device__ int   g_cursor[MAXN];
__device__ int   g_esrc[MAXEDG];
__device__ int   g_src32[MAXE];
__device__ int   g_dst32[MAXE];
__device__ int   g_is64;
// W1 pre-split to bf16 hi/lo, transposed to [n][k]; reinterpreted as packed
// bf16x2 words (word w = k-pair {2w, 2w+1}) for the MMA B operand.
__device__ __align__(16) unsigned short g_w1hi[(size_t)HC * F_IN];
__device__ __align__(16) unsigned short g_w1lo[(size_t)HC * F_IN];

// ---------------- edge dtype detection ------------------------------------
__global__ void k_detect(const void* __restrict__ ei, int E, int N) {
    if (blockIdx.x == 0 && threadIdx.x == 0) {
        const long long* p = (const long long*)ei;
        int ok64 = 1;
        int n = E < 64 ? E : 64;
        for (int i = 0; i < n; i++) {
            long long v = p[i];
            if (v < 0 || v >= (long long)N) { ok64 = 0; break; }
        }
        g_is64 = ok64;
    }
}

__global__ void k_init_deg(int n) {
    int i = blockIdx.x * blockDim.x + threadIdx.x;
    if (i < n) g_deg[i] = 1;   // self loop
}

// fused: dtype-normalize edges AND count in-degrees in one pass
__global__ void k_convert_count(const void* __restrict__ ei, int E, int N) {
    int i = blockIdx.x * blockDim.x + threadIdx.x;
    if (i >= E) return;
    int s, d;
    if (g_is64) {
        const long long* p = (const long long*)ei;
        s = (int)p[i];
        d = (int)p[E + i];
    } else {
        const int* p = (const int*)ei;
        s = p[i];
        d = p[E + i];
    }
    s = s < 0 ? 0 : (s >= N ? N - 1 : s);
    d = d < 0 ? 0 : (d >= N ? N - 1 : d);
    g_src32[i] = s;
    g_dst32[i] = d;
    atomicAdd(&g_deg[d], 1);
}

// single-block exclusive scan of g_deg -> g_rowptr (pure scan: keep the
// per-thread loop a simple batched-load sequence; NO scattered stores here)
__global__ void k_scan(int n) {
    __shared__ int s[1024];
    int t = threadIdx.x;
    int chunk = (n + 1023) >> 10;
    int b = t * chunk;
    int e = min(b + chunk, n);
    int sum = 0;
    for (int i = b; i < e; i++) sum += g_deg[i];
    s[t] = sum;
    __syncthreads();
    for (int off = 1; off < 1024; off <<= 1) {
        int v = (t >= off) ? s[t - off] : 0;
        __syncthreads();
        s[t] += v;
        __syncthreads();
    }
    int run = (t == 0) ? 0 : s[t - 1];
    for (int i = b; i < e; i++) { g_rowptr[i] = run; run += g_deg[i]; }
    if (t == 1023) g_rowptr[n] = s[1023];
}

// grid-wide: place self loop first, set cursor (fast scattered writes)
__global__ void k_selfloop(int n) {
    int i = blockIdx.x * blockDim.x + threadIdx.x;
    if (i < n) {
        int r = g_rowptr[i];
        g_esrc[r] = i;
        g_cursor[i] = r + 1;
    }
}

__global__ void k_scatter(int E) {
    int i = blockIdx.x * blockDim.x + threadIdx.x;
    if (i < E) {
        int d = g_dst32[i];
        int p = atomicAdd(&g_cursor[d], 1);
        g_esrc[p] = g_src32[i];
    }
}

// ---------------- W1 pre-split: fp32 [k][n] -> bf16 hi/lo [n][k] ------------
__global__ void k_prepw(const float* __restrict__ W1) {
    int i = blockIdx.x * blockDim.x + threadIdx.x;
    if (i >= F_IN * HC) return;
    int k = i >> 8;        // row in W1 (k index), HC=256
    int n = i & 255;       // col in W1 (output channel)
    float v = W1[i];
    unsigned short hb, lb;
    asm("cvt.rn.bf16.f32 %0, %1;" : "=h"(hb) : "f"(v));
    float r = v - __uint_as_float((uint32_t)hb << 16);
    asm("cvt.rn.bf16.f32 %0, %1;" : "=h"(lb) : "f"(r));
    g_w1hi[(size_t)n * F_IN + k] = hb;
    g_w1lo[(size_t)n * F_IN + k] = lb;
}

// ---------------- GEMM1: legacy mma.sync bf16 m16n8k16, 3-term split --------
// h1[M x 256] = x[M x 512] @ W1[512 x 256]; ah*bh + ah*bl + al*bh.
// Software-pipelined: next tile's global loads prefetched during MMA compute.
__device__ __forceinline__ void mma16(float4& c, unsigned a0, unsigned a1,
                                      unsigned a2, unsigned a3,
                                      unsigned b0, unsigned b1) {
    asm volatile(
        "mma.sync.aligned.m16n8k16.row.col.f32.bf16.bf16.f32 "
        "{%0,%1,%2,%3}, {%4,%5,%6,%7}, {%8,%9}, {%0,%1,%2,%3};"
        : "+f"(c.x), "+f"(c.y), "+f"(c.z), "+f"(c.w)
        : "r"(a0), "r"(a1), "r"(a2), "r"(a3), "r"(b0), "r"(b1));
}

#define PITCH 136   // smem pitch in words: fragment gathers conflict-free

__global__ __launch_bounds__(256) void k_gemm1_bf(const float* __restrict__ A, int M) {
    // packed bf16x2 tiles, word index kw = k-pair, kw in [0,8)
    __shared__ unsigned As2h[8][PITCH];
    __shared__ unsigned As2l[8][PITCH];
    __shared__ unsigned Bs2h[8][PITCH];
    __shared__ unsigned Bs2l[8][PITCH];

    int t    = threadIdx.x;
    int warp = t >> 5, lane = t & 31;
    int wm   = (warp >> 2) * 64;     // warp M offset (2 warps in M)
    int wn   = (warp & 3) * 32;      // warp N offset (4 warps in N)
    int gq   = lane >> 2;            // group id 0..7
    int tq   = lane & 3;             // thread-in-group 0..3
    int bm   = blockIdx.x * 128;
    int bn   = blockIdx.y * 128;

    const unsigned* w1h = (const unsigned*)g_w1hi;   // [n][256] packed words
    const unsigned* w1l = (const unsigned*)g_w1lo;

    // per-thread load coordinates (A: 2 float4 / iter, B: 2 uint2-pairs / iter)
    int a_row[2];
    const float* a_ptr[2];
    int b_kw[2];
    const unsigned* bh_ptr[2];
    const unsigned* bl_ptr[2];
#pragma unroll
    for (int i = 0; i < 2; i++) {
        int idx = t + i * 256;
        a_row[i] = idx >> 2;
        int a_c4 = (idx & 3) * 4;
        int gr = bm + a_row[i];
        a_ptr[i] = (gr < M) ? (A + (size_t)gr * F_IN + a_c4) : 0;
        int e = t + i * 256;
        int col = e >> 2;
        b_kw[i] = (e & 3) * 2;
        size_t gi = (size_t)(bn + col) * 256 + b_kw[i];
        bh_ptr[i] = w1h + gi;
        bl_ptr[i] = w1l + gi;
    }

    float4 acc[4][4];
#pragma unroll
    for (int i = 0; i < 4; i++)
#pragma unroll
        for (int j = 0; j < 4; j++) acc[i][j] = make_float4(0.f, 0.f, 0.f, 0.f);

    // prologue: load tile kt=0
    float4 pa[2];
    uint2  pbh[2], pbl[2];
#pragma unroll
    for (int i = 0; i < 2; i++) {
        pa[i] = a_ptr[i] ? *(const float4*)(a_ptr[i]) : make_float4(0.f, 0.f, 0.f, 0.f);
        pbh[i] = *(const uint2*)(bh_ptr[i]);
        pbl[i] = *(const uint2*)(bl_ptr[i]);
    }

    for (int kt = 0; kt < F_IN; kt += 16) {
        // store current prefetched tile to smem (convert A on the fly)
#pragma unroll
        for (int i = 0; i < 2; i++) {
            int idx = t + i * 256;
            int row = a_row[i];
            int kw  = (idx & 3) * 2;
            float4 v = pa[i];
            unsigned ph01, ph23, pl01, pl23;
            asm("cvt.rn.bf16x2.f32 %0, %1, %2;" : "=r"(ph01) : "f"(v.y), "f"(v.x));
            asm("cvt.rn.bf16x2.f32 %0, %1, %2;" : "=r"(ph23) : "f"(v.w), "f"(v.z));
            float r0 = v.x - __uint_as_float(ph01 << 16);
            float r1 = v.y - __uint_as_float(ph01 & 0xffff0000u);
            float r2 = v.z - __uint_as_float(ph23 << 16);
            float r3 = v.w - __uint_as_float(ph23 & 0xffff0000u);
            asm("cvt.rn.bf16x2.f32 %0, %1, %2;" : "=r"(pl01) : "f"(r1), "f"(r0));
            asm("cvt.rn.bf16x2.f32 %0, %1, %2;" : "=r"(pl23) : "f"(r3), "f"(r2));
            As2h[kw][row]     = ph01;
            As2h[kw + 1][row] = ph23;
            As2l[kw][row]     = pl01;
            As2l[kw + 1][row] = pl23;
            int e = t + i * 256;
            int col = e >> 2;
            int kw2 = b_kw[i];
            Bs2h[kw2][col]     = pbh[i].x;
            Bs2h[kw2 + 1][col] = pbh[i].y;
            Bs2l[kw2][col]     = pbl[i].x;
            Bs2l[kw2 + 1][col] = pbl[i].y;
        }
        __syncthreads();

        // prefetch next tile's globals (in flight during the MMAs below)
        if (kt + 16 < F_IN) {
            int koff = kt + 16;
#pragma unroll
            for (int i = 0; i < 2; i++) {
                pa[i] = a_ptr[i] ? *(const float4*)(a_ptr[i] + koff)
                                 : make_float4(0.f, 0.f, 0.f, 0.f);
                pbh[i] = *(const uint2*)(bh_ptr[i] + (koff >> 1));
                pbl[i] = *(const uint2*)(bl_ptr[i] + (koff >> 1));
            }
        }

        unsigned ah[4][4], al[4][4], bh[4][2], bl[4][2];
#pragma unroll
        for (int mi = 0; mi < 4; mi++) {
            int m = wm + mi * 16 + gq;
            ah[mi][0] = As2h[tq][m];
            ah[mi][1] = As2h[tq][m + 8];
            ah[mi][2] = As2h[tq + 4][m];
            ah[mi][3] = As2h[tq + 4][m + 8];
            al[mi][0] = As2l[tq][m];
            al[mi][1] = As2l[tq][m + 8];
            al[mi][2] = As2l[tq + 4][m];
            al[mi][3] = As2l[tq + 4][m + 8];
        }
#pragma unroll
        for (int nj = 0; nj < 4; nj++) {
            int n = wn + nj * 8 + gq;
            bh[nj][0] = Bs2h[tq][n];
            bh[nj][1] = Bs2h[tq + 4][n];
            bl[nj][0] = Bs2l[tq][n];
            bl[nj][1] = Bs2l[tq + 4][n];
        }
#pragma unroll
        for (int mi = 0; mi < 4; mi++)
#pragma unroll
            for (int nj = 0; nj < 4; nj++) {
                mma16(acc[mi][nj], ah[mi][0], ah[mi][1], ah[mi][2], ah[mi][3],
                      bl[nj][0], bl[nj][1]);                    // hi*lo
                mma16(acc[mi][nj], al[mi][0], al[mi][1], al[mi][2], al[mi][3],
                      bh[nj][0], bh[nj][1]);                    // lo*hi
                mma16(acc[mi][nj], ah[mi][0], ah[mi][1], ah[mi][2], ah[mi][3],
                      bh[nj][0], bh[nj][1]);                    // hi*hi
            }
        __syncthreads();
    }

    // epilogue: c0,c1 (row g, cols 2tq,2tq+1), c2,c3 (row g+8)
#pragma unroll
    for (int mi = 0; mi < 4; mi++) {
        int row0 = bm + wm + mi * 16 + gq;
        int row1 = row0 + 8;
#pragma unroll
        for (int nj = 0; nj < 4; nj++) {
            int col = bn + wn + nj * 8 + tq * 2;
            if (row0 < M)
                *(float2*)(g_h1 + (size_t)row0 * HC + col) =
                    make_float2(acc[mi][nj].x, acc[mi][nj].y);
            if (row1 < M)
                *(float2*)(g_h1 + (size_t)row1 * HC + col) =
                    make_float2(acc[mi][nj].z, acc[mi][nj].w);
        }
    }
}

// ---------------- attention coefficients layer 1 ---------------------------
__global__ void k_attn1(const float* __restrict__ att_src,
                        const float* __restrict__ att_dst, int N) {
    int warp = (blockIdx.x * blockDim.x + threadIdx.x) >> 5;
    int lane = threadIdx.x & 31;
    if (warp >= N) return;
    const float4* hp = (const float4*)(g_h1 + (size_t)warp * HC);
    float4 h0 = hp[lane * 2], h1v = hp[lane * 2 + 1];
    int base = lane * 8;
    float4 s0 = *(const float4*)(att_src + base);
    float4 s1 = *(const float4*)(att_src + base + 4);
    float4 d0 = *(const float4*)(att_dst + base);
    float4 d1 = *(const float4*)(att_dst + base + 4);
    float ps = h0.x * s0.x + h0.y * s0.y + h0.z * s0.z + h0.w * s0.w
             + h1v.x * s1.x + h1v.y * s1.y + h1v.z * s1.z + h1v.w * s1.w;
    float pd = h0.x * d0.x + h0.y * d0.y + h0.z * d0.z + h0.w * d0.w
             + h1v.x * d1.x + h1v.y * d1.y + h1v.z * d1.z + h1v.w * d1.w;
#pragma unroll
    for (int o = 4; o; o >>= 1) {
        ps += __shfl_xor_sync(0xffffffffu, ps, o);
        pd += __shfl_xor_sync(0xffffffffu, pd, o);
    }
    if ((lane & 7) == 0) {
        int h = lane >> 3;
        g_asrc1[warp * NH + h] = ps;
        g_adst1[warp * NH + h] = pd;
    }
}

// ---------------- layer-1 aggregation: warp/node, online softmax -----------
__global__ void k_agg1(const float* __restrict__ b1, int N) {
    int node = (blockIdx.x * blockDim.x + threadIdx.x) >> 5;
    int lane = threadIdx.x & 31;
    if (node >= N) return;
    int head = lane >> 3;
    int start = g_rowptr[node], end = g_rowptr[node + 1];
    float ad = g_adst1[node * NH + head];
    float m = NEG_INF, d = 0.f;
    float acc[8];
#pragma unroll
    for (int j = 0; j < 8; j++) acc[j] = 0.f;

    for (int e = start; e < end; e++) {
        int s = g_esrc[e];
        float al = g_asrc1[s * NH + head] + ad;
        al = al > 0.f ? al : 0.2f * al;             // leaky_relu
        float mn = fmaxf(m, al);
        float sc = __expf(m - mn);                  // 0 on first edge
        float w  = __expf(al - mn);
        d = d * sc + w;
        const float4* hp = (const float4*)(g_h1 + (size_t)s * HC) + lane * 2;
        float4 v0 = hp[0], v1 = hp[1];
        acc[0] = acc[0] * sc + w * v0.x;
        acc[1] = acc[1] * sc + w * v0.y;
        acc[2] = acc[2] * sc + w * v0.z;
        acc[3] = acc[3] * sc + w * v0.w;
        acc[4] = acc[4] * sc + w * v1.x;
        acc[5] = acc[5] * sc + w * v1.y;
        acc[6] = acc[6] * sc + w * v1.z;
        acc[7] = acc[7] * sc + w * v1.w;
        m = mn;
    }
    float inv = 1.f / (d + 1e-16f);
    int col = lane * 8;
#pragma unroll
    for (int j = 0; j < 8; j++) {
        float v = acc[j] * inv + __ldg(b1 + col + j);
        acc[j] = v > 0.f ? v : (expf(v) - 1.f);     // elu
    }
    float4* op = (float4*)(g_h2 + (size_t)node * HC + col);
    op[0] = make_float4(acc[0], acc[1], acc[2], acc[3]);
    op[1] = make_float4(acc[4], acc[5], acc[6], acc[7]);
}

// ---------------- GEMM2: h3[M x 40] = h2[M x 256] @ W2[256 x 40] -----------
__global__ __launch_bounds__(256) void k_gemm2(const float* __restrict__ W2, int M) {
    __shared__ float hs[64][65];
    __shared__ float ws[64][OUTC];
    int t = threadIdx.x;
    int bm = blockIdx.x * 64;
    int cg = t & 7;
    int rg = t >> 3;
    float acc[2][5];
#pragma unroll
    for (int r = 0; r < 2; r++)
#pragma unroll
        for (int j = 0; j < 5; j++) acc[r][j] = 0.f;

    for (int kt = 0; kt < HC; kt += 64) {
#pragma unroll
        for (int i = 0; i < 4; i++) {
            int idx = t + i * 256;
            int row = idx >> 4;
            int c4  = (idx & 15) * 4;
            float4 v = make_float4(0.f, 0.f, 0.f, 0.f);
            int gr = bm + row;
            if (gr < M) v = *(const float4*)(g_h2 + (size_t)gr * HC + kt + c4);
            hs[row][c4 + 0] = v.x;
            hs[row][c4 + 1] = v.y;
            hs[row][c4 + 2] = v.z;
            hs[row][c4 + 3] = v.w;
        }
#pragma unroll
        for (int i = 0; i < 10; i++) {
            int idx = t + i * 256;
            int kr = idx / OUTC;
            int c  = idx - kr * OUTC;
            ws[kr][c] = W2[(size_t)(kt + kr) * OUTC + c];
        }
        __syncthreads();
#pragma unroll
        for (int k = 0; k < 64; k++) {
            float h0 = hs[rg * 2][k];
            float h1v = hs[rg * 2 + 1][k];
#pragma unroll
            for (int j = 0; j < 5; j++) {
                float w = ws[k][cg * 5 + j];
                acc[0][j] += h0 * w;
                acc[1][j] += h1v * w;
            }
        }
        __syncthreads();
    }
#pragma unroll
    for (int r = 0; r < 2; r++) {
        int gr = bm + rg * 2 + r;
        if (gr >= M) continue;
#pragma unroll
        for (int j = 0; j < 5; j++)
            g_h3[(size_t)gr * OUTC + cg * 5 + j] = acc[r][j];
    }
}

// ---------------- attention coefficients layer 2 ---------------------------
__global__ void k_attn2(const float* __restrict__ att_src,
                        const float* __restrict__ att_dst, int N) {
    int node = (blockIdx.x * blockDim.x + threadIdx.x) >> 5;
    int lane = threadIdx.x & 31;
    if (node >= N) return;
    const float* hp = g_h3 + (size_t)node * OUTC;
    float ps = hp[lane] * __ldg(att_src + lane);
    float pd = hp[lane] * __ldg(att_dst + lane);
    if (lane < 8) {
        ps += hp[32 + lane] * __ldg(att_src + 32 + lane);
        pd += hp[32 + lane] * __ldg(att_dst + 32 + lane);
    }
#pragma unroll
    for (int o = 16; o; o >>= 1) {
        ps += __shfl_xor_sync(0xffffffffu, ps, o);
        pd += __shfl_xor_sync(0xffffffffu, pd, o);
    }
    if (lane == 0) { g_asrc2[node] = ps; g_adst2[node] = pd; }
}

// ---------------- layer-2 aggregation + bias + log_softmax -----------------
__global__ void k_agg2(const float* __restrict__ b2, float* __restrict__ out, int N) {
    int node = (blockIdx.x * blockDim.x + threadIdx.x) >> 5;
    int lane = threadIdx.x & 31;
    if (node >= N) return;
    int start = g_rowptr[node], end = g_rowptr[node + 1];
    float ad = g_adst2[node];
    float m = NEG_INF, d = 0.f;
    float a0 = 0.f, a1 = 0.f;
    for (int e = start; e < end; e++) {
        int s = g_esrc[e];
        float al = g_asrc2[s] + ad;
        al = al > 0.f ? al : 0.2f * al;
        float mn = fmaxf(m, al);
        float sc = __expf(m - mn);
        float w  = __expf(al - mn);
        d = d * sc + w;
        const float* hp = g_h3 + (size_t)s * OUTC;
        float v0 = hp[lane];
        float v1 = (lane < 8) ? hp[32 + lane] : 0.f;
        a0 = a0 * sc + w * v0;
        a1 = a1 * sc + w * v1;
        m = mn;
    }
    float inv = 1.f / (d + 1e-16f);
    float o0 = a0 * inv + __ldg(b2 + lane);
    float o1 = (lane < 8) ? (a1 * inv + __ldg(b2 + 32 + lane)) : NEG_INF;
    float mx = fmaxf(o0, o1);
#pragma unroll
    for (int o = 16; o; o >>= 1) mx = fmaxf(mx, __shfl_xor_sync(0xffffffffu, mx, o));
    float se = expf(o0 - mx) + ((lane < 8) ? expf(o1 - mx) : 0.f);
#pragma unroll
    for (int o = 16; o; o >>= 1) se += __shfl_xor_sync(0xffffffffu, se, o);
    float L = logf(se);
    float* op = out + (size_t)node * OUTC;
    op[lane] = o0 - mx - L;
    if (lane < 8) op[32 + lane] = o1 - mx - L;
}

// ---------------- launch ----------------------------------------------------
extern "C" void kernel_launch(void* const* d_in, const int* in_sizes, int n_in,
                              void* d_out, int out_size) {
    const float* x   = (const float*)d_in[0];
    const void*  ei  = d_in[1];
    const float* W1  = (const float*)d_in[2];
    const float* as1 = (const float*)d_in[3];
    const float* ad1 = (const float*)d_in[4];
    const float* b1  = (const float*)d_in[5];
    const float* W2  = (const float*)d_in[6];
    const float* as2 = (const float*)d_in[7];
    const float* ad2 = (const float*)d_in[8];
    const float* b2  = (const float*)d_in[9];
    float*       out = (float*)d_out;

    int N = in_sizes[0] / F_IN;
    int E = in_sizes[1] / 2;

    int nb = (N + 255) / 256;
    int eb = (E + 255) / 256;
    int wb = (N + 7) / 8;   // one warp per node, 8 warps per block

    // Edge dtype normalization + CSR by destination (self loops included)
    k_detect<<<1, 32>>>(ei, E, N);
    k_init_deg<<<nb, 256>>>(N);
    k_convert_count<<<eb, 256>>>(ei, E, N);
    k_scan<<<1, 1024>>>(N);
    k_selfloop<<<nb, 256>>>(N);
    k_scatter<<<eb, 256>>>(E);

    // Layer 1
    k_prepw<<<(F_IN * HC + 255) / 256, 256>>>(W1);
    dim3 g1((N + 127) / 128, HC / 128);
    k_gemm1_bf<<<g1, 256>>>(x, N);
    k_attn1<<<wb, 256>>>(as1, ad1, N);
    k_agg1<<<wb, 256>>>(b1, N);

    // Layer 2
    k_gemm2<<<(N + 63) / 64, 256>>>(W2, N);
    k_attn2<<<wb, 256>>>(as2, ad2, N);
    k_agg2<<<wb, 256>>>(b2, out, N);
}

// round 17
// speedup vs baseline: 1.2414x; 1.1000x over previous
#include <cuda_runtime.h>
#include <math.h>
#include <stdint.h>

// Problem constants (GAT: N=50000 nodes, E=800000 edges, F_in=512, H=4, C=64, OUT=40)
#define F_IN   512
#define HC     256      // H*C for layer 1
#define NH     4
#define OUTC   40
#define MAXN   50000
#define MAXE   800000
#define MAXEDG (MAXE + MAXN)   // + self loops

#define NEG_INF __int_as_float(0xff800000u)

// ---------------- scratch (static device globals; no allocation allowed) ----
__device__ __align__(16) float g_h1[(size_t)MAXN * HC];   // x@W1
__device__ __align__(16) float g_h2[(size_t)MAXN * HC];   // layer1 output (post elu)
__device__ __align__(16) float g_h3[(size_t)MAXN * OUTC]; // h2@W2
__device__ float g_asrc1[MAXN * NH];
__device__ float g_adst1[MAXN * NH];
__device__ float g_asrc2[MAXN];
__device__ float g_adst2[MAXN];
__device__ int   g_deg[MAXN];
__device__ int   g_rowptr[MAXN + 1];
__device__ int   g_cursor[MAXN];
__device__ int   g_esrc[MAXEDG];
__device__ int   g_src32[MAXE];
__device__ int   g_dst32[MAXE];
__device__ int   g_is64;
#define SCAN_B 128
#define SCAN_T 256
__device__ int   g_bsum[SCAN_B];
// W1 pre-split to bf16 hi/lo, transposed to [n][k]; reinterpreted as packed
// bf16x2 words (word w = k-pair {2w, 2w+1}) for the MMA B operand.
__device__ __align__(16) unsigned short g_w1hi[(size_t)HC * F_IN];
__device__ __align__(16) unsigned short g_w1lo[(size_t)HC * F_IN];

// ---------------- edge dtype detection ------------------------------------
__global__ void k_detect(const void* __restrict__ ei, int E, int N) {
    if (blockIdx.x == 0 && threadIdx.x == 0) {
        const long long* p = (const long long*)ei;
        int ok64 = 1;
        int n = E < 64 ? E : 64;
        for (int i = 0; i < n; i++) {
            long long v = p[i];
            if (v < 0 || v >= (long long)N) { ok64 = 0; break; }
        }
        g_is64 = ok64;
    }
}

__global__ void k_init_deg(int n) {
    int i = blockIdx.x * blockDim.x + threadIdx.x;
    if (i < n) g_deg[i] = 1;   // self loop
}

// fused: dtype-normalize edges AND count in-degrees in one pass
__global__ void k_convert_count(const void* __restrict__ ei, int E, int N) {
    int i = blockIdx.x * blockDim.x + threadIdx.x;
    if (i >= E) return;
    int s, d;
    if (g_is64) {
        const long long* p = (const long long*)ei;
        s = (int)p[i];
        d = (int)p[E + i];
    } else {
        const int* p = (const int*)ei;
        s = p[i];
        d = p[E + i];
    }
    s = s < 0 ? 0 : (s >= N ? N - 1 : s);
    d = d < 0 ? 0 : (d >= N ? N - 1 : d);
    g_src32[i] = s;
    g_dst32[i] = d;
    atomicAdd(&g_deg[d], 1);
}

// ---------------- parallel 3-phase scan over g_deg -------------------------
// Phase A: per-block partial sums (coalesced)
__global__ void k_scan_a(int n) {
    __shared__ int s[SCAN_T];
    int chunk = (n + SCAN_B - 1) / SCAN_B;
    int b0 = blockIdx.x * chunk;
    int b1 = min(b0 + chunk, n);
    int sum = 0;
    for (int i = b0 + threadIdx.x; i < b1; i += SCAN_T) sum += g_deg[i];
    s[threadIdx.x] = sum;
    __syncthreads();
    for (int off = SCAN_T / 2; off; off >>= 1) {
        if (threadIdx.x < off) s[threadIdx.x] += s[threadIdx.x + off];
        __syncthreads();
    }
    if (threadIdx.x == 0) g_bsum[blockIdx.x] = s[0];
}

// Phase B: exclusive scan of the 128 block sums (one small block)
__global__ void k_scan_b() {
    __shared__ int s[SCAN_B];
    int t = threadIdx.x;
    s[t] = g_bsum[t];
    __syncthreads();
    for (int off = 1; off < SCAN_B; off <<= 1) {
        int v = (t >= off) ? s[t - off] : 0;
        __syncthreads();
        s[t] += v;
        __syncthreads();
    }
    g_bsum[t] = (t == 0) ? 0 : s[t - 1];
}

// Phase C: re-scan chunk, write rowptr + self-loop entry + cursor
__global__ void k_scan_c(int n) {
    __shared__ int s[SCAN_T];
    __shared__ int base;
    int chunk = (n + SCAN_B - 1) / SCAN_B;
    int b0 = blockIdx.x * chunk;
    int b1 = min(b0 + chunk, n);
    if (threadIdx.x == 0) base = g_bsum[blockIdx.x];
    int tchunk = (chunk + SCAN_T - 1) / SCAN_T;
    int t0 = min(b0 + threadIdx.x * tchunk, b1);
    int t1 = min(t0 + tchunk, b1);
    int sum = 0;
    for (int i = t0; i < t1; i++) sum += g_deg[i];
    s[threadIdx.x] = sum;
    __syncthreads();
    for (int off = 1; off < SCAN_T; off <<= 1) {
        int v = (threadIdx.x >= off) ? s[threadIdx.x - off] : 0;
        __syncthreads();
        s[threadIdx.x] += v;
        __syncthreads();
    }
    int run = base + (threadIdx.x == 0 ? 0 : s[threadIdx.x - 1]);
    for (int i = t0; i < t1; i++) {
        g_rowptr[i] = run;
        g_esrc[run] = i;          // self loop placed first
        g_cursor[i] = run + 1;
        run += g_deg[i];
    }
    if (t1 == n) g_rowptr[n] = run;   // total (threads past the end carry total too)
}

__global__ void k_scatter(int E) {
    int i = blockIdx.x * blockDim.x + threadIdx.x;
    if (i < E) {
        int d = g_dst32[i];
        int p = atomicAdd(&g_cursor[d], 1);
        g_esrc[p] = g_src32[i];
    }
}

// ---------------- W1 pre-split: fp32 [k][n] -> bf16 hi/lo [n][k] ------------
__global__ void k_prepw(const float* __restrict__ W1) {
    int i = blockIdx.x * blockDim.x + threadIdx.x;
    if (i >= F_IN * HC) return;
    int k = i >> 8;        // row in W1 (k index), HC=256
    int n = i & 255;       // col in W1 (output channel)
    float v = W1[i];
    unsigned short hb, lb;
    asm("cvt.rn.bf16.f32 %0, %1;" : "=h"(hb) : "f"(v));
    float r = v - __uint_as_float((uint32_t)hb << 16);
    asm("cvt.rn.bf16.f32 %0, %1;" : "=h"(lb) : "f"(r));
    g_w1hi[(size_t)n * F_IN + k] = hb;
    g_w1lo[(size_t)n * F_IN + k] = lb;
}

// ---------------- GEMM1: legacy mma.sync bf16 m16n8k16, 3-term split --------
// h1[M x 256] = x[M x 512] @ W1[512 x 256]; ah*bh + ah*bl + al*bh.
// Software-pipelined: next tile's global loads prefetched during MMA compute.
__device__ __forceinline__ void mma16(float4& c, unsigned a0, unsigned a1,
                                      unsigned a2, unsigned a3,
                                      unsigned b0, unsigned b1) {
    asm volatile(
        "mma.sync.aligned.m16n8k16.row.col.f32.bf16.bf16.f32 "
        "{%0,%1,%2,%3}, {%4,%5,%6,%7}, {%8,%9}, {%0,%1,%2,%3};"
        : "+f"(c.x), "+f"(c.y), "+f"(c.z), "+f"(c.w)
        : "r"(a0), "r"(a1), "r"(a2), "r"(a3), "r"(b0), "r"(b1));
}

#define PITCH 136   // smem pitch in words: fragment gathers conflict-free

__global__ __launch_bounds__(256) void k_gemm1_bf(const float* __restrict__ A, int M) {
    // packed bf16x2 tiles, word index kw = k-pair, kw in [0,8)
    __shared__ unsigned As2h[8][PITCH];
    __shared__ unsigned As2l[8][PITCH];
    __shared__ unsigned Bs2h[8][PITCH];
    __shared__ unsigned Bs2l[8][PITCH];

    int t    = threadIdx.x;
    int warp = t >> 5, lane = t & 31;
    int wm   = (warp >> 2) * 64;     // warp M offset (2 warps in M)
    int wn   = (warp & 3) * 32;      // warp N offset (4 warps in N)
    int gq   = lane >> 2;            // group id 0..7
    int tq   = lane & 3;             // thread-in-group 0..3
    int bm   = blockIdx.x * 128;
    int bn   = blockIdx.y * 128;

    const unsigned* w1h = (const unsigned*)g_w1hi;   // [n][256] packed words
    const unsigned* w1l = (const unsigned*)g_w1lo;

    // per-thread load coordinates (A: 2 float4 / iter, B: 2 uint2-pairs / iter)
    int a_row[2];
    const float* a_ptr[2];
    int b_kw[2];
    const unsigned* bh_ptr[2];
    const unsigned* bl_ptr[2];
#pragma unroll
    for (int i = 0; i < 2; i++) {
        int idx = t + i * 256;
        a_row[i] = idx >> 2;
        int a_c4 = (idx & 3) * 4;
        int gr = bm + a_row[i];
        a_ptr[i] = (gr < M) ? (A + (size_t)gr * F_IN + a_c4) : 0;
        int e = t + i * 256;
        int col = e >> 2;
        b_kw[i] = (e & 3) * 2;
        size_t gi = (size_t)(bn + col) * 256 + b_kw[i];
        bh_ptr[i] = w1h + gi;
        bl_ptr[i] = w1l + gi;
    }

    float4 acc[4][4];
#pragma unroll
    for (int i = 0; i < 4; i++)
#pragma unroll
        for (int j = 0; j < 4; j++) acc[i][j] = make_float4(0.f, 0.f, 0.f, 0.f);

    // prologue: load tile kt=0
    float4 pa[2];
    uint2  pbh[2], pbl[2];
#pragma unroll
    for (int i = 0; i < 2; i++) {
        pa[i] = a_ptr[i] ? *(const float4*)(a_ptr[i]) : make_float4(0.f, 0.f, 0.f, 0.f);
        pbh[i] = *(const uint2*)(bh_ptr[i]);
        pbl[i] = *(const uint2*)(bl_ptr[i]);
    }

    for (int kt = 0; kt < F_IN; kt += 16) {
        // store current prefetched tile to smem (convert A on the fly)
#pragma unroll
        for (int i = 0; i < 2; i++) {
            int idx = t + i * 256;
            int row = a_row[i];
            int kw  = (idx & 3) * 2;
            float4 v = pa[i];
            unsigned ph01, ph23, pl01, pl23;
            asm("cvt.rn.bf16x2.f32 %0, %1, %2;" : "=r"(ph01) : "f"(v.y), "f"(v.x));
            asm("cvt.rn.bf16x2.f32 %0, %1, %2;" : "=r"(ph23) : "f"(v.w), "f"(v.z));
            float r0 = v.x - __uint_as_float(ph01 << 16);
            float r1 = v.y - __uint_as_float(ph01 & 0xffff0000u);
            float r2 = v.z - __uint_as_float(ph23 << 16);
            float r3 = v.w - __uint_as_float(ph23 & 0xffff0000u);
            asm("cvt.rn.bf16x2.f32 %0, %1, %2;" : "=r"(pl01) : "f"(r1), "f"(r0));
            asm("cvt.rn.bf16x2.f32 %0, %1, %2;" : "=r"(pl23) : "f"(r3), "f"(r2));
            As2h[kw][row]     = ph01;
            As2h[kw + 1][row] = ph23;
            As2l[kw][row]     = pl01;
            As2l[kw + 1][row] = pl23;
            int e = t + i * 256;
            int col = e >> 2;
            int kw2 = b_kw[i];
            Bs2h[kw2][col]     = pbh[i].x;
            Bs2h[kw2 + 1][col] = pbh[i].y;
            Bs2l[kw2][col]     = pbl[i].x;
            Bs2l[kw2 + 1][col] = pbl[i].y;
        }
        __syncthreads();

        // prefetch next tile's globals (in flight during the MMAs below)
        if (kt + 16 < F_IN) {
            int koff = kt + 16;
#pragma unroll
            for (int i = 0; i < 2; i++) {
                pa[i] = a_ptr[i] ? *(const float4*)(a_ptr[i] + koff)
                                 : make_float4(0.f, 0.f, 0.f, 0.f);
                pbh[i] = *(const uint2*)(bh_ptr[i] + (koff >> 1));
                pbl[i] = *(const uint2*)(bl_ptr[i] + (koff >> 1));
            }
        }

        unsigned ah[4][4], al[4][4], bh[4][2], bl[4][2];
#pragma unroll
        for (int mi = 0; mi < 4; mi++) {
            int m = wm + mi * 16 + gq;
            ah[mi][0] = As2h[tq][m];
            ah[mi][1] = As2h[tq][m + 8];
            ah[mi][2] = As2h[tq + 4][m];
            ah[mi][3] = As2h[tq + 4][m + 8];
            al[mi][0] = As2l[tq][m];
            al[mi][1] = As2l[tq][m + 8];
            al[mi][2] = As2l[tq + 4][m];
            al[mi][3] = As2l[tq + 4][m + 8];
        }
#pragma unroll
        for (int nj = 0; nj < 4; nj++) {
            int n = wn + nj * 8 + gq;
            bh[nj][0] = Bs2h[tq][n];
            bh[nj][1] = Bs2h[tq + 4][n];
            bl[nj][0] = Bs2l[tq][n];
            bl[nj][1] = Bs2l[tq + 4][n];
        }
#pragma unroll
        for (int mi = 0; mi < 4; mi++)
#pragma unroll
            for (int nj = 0; nj < 4; nj++) {
                mma16(acc[mi][nj], ah[mi][0], ah[mi][1], ah[mi][2], ah[mi][3],
                      bl[nj][0], bl[nj][1]);                    // hi*lo
                mma16(acc[mi][nj], al[mi][0], al[mi][1], al[mi][2], al[mi][3],
                      bh[nj][0], bh[nj][1]);                    // lo*hi
                mma16(acc[mi][nj], ah[mi][0], ah[mi][1], ah[mi][2], ah[mi][3],
                      bh[nj][0], bh[nj][1]);                    // hi*hi
            }
        __syncthreads();
    }

    // epilogue: c0,c1 (row g, cols 2tq,2tq+1), c2,c3 (row g+8)
#pragma unroll
    for (int mi = 0; mi < 4; mi++) {
        int row0 = bm + wm + mi * 16 + gq;
        int row1 = row0 + 8;
#pragma unroll
        for (int nj = 0; nj < 4; nj++) {
            int col = bn + wn + nj * 8 + tq * 2;
            if (row0 < M)
                *(float2*)(g_h1 + (size_t)row0 * HC + col) =
                    make_float2(acc[mi][nj].x, acc[mi][nj].y);
            if (row1 < M)
                *(float2*)(g_h1 + (size_t)row1 * HC + col) =
                    make_float2(acc[mi][nj].z, acc[mi][nj].w);
        }
    }
}

// ---------------- attention coefficients layer 1 ---------------------------
__global__ void k_attn1(const float* __restrict__ att_src,
                        const float* __restrict__ att_dst, int N) {
    int warp = (blockIdx.x * blockDim.x + threadIdx.x) >> 5;
    int lane = threadIdx.x & 31;
    if (warp >= N) return;
    const float4* hp = (const float4*)(g_h1 + (size_t)warp * HC);
    float4 h0 = hp[lane * 2], h1v = hp[lane * 2 + 1];
    int base = lane * 8;
    float4 s0 = *(const float4*)(att_src + base);
    float4 s1 = *(const float4*)(att_src + base + 4);
    float4 d0 = *(const float4*)(att_dst + base);
    float4 d1 = *(const float4*)(att_dst + base + 4);
    float ps = h0.x * s0.x + h0.y * s0.y + h0.z * s0.z + h0.w * s0.w
             + h1v.x * s1.x + h1v.y * s1.y + h1v.z * s1.z + h1v.w * s1.w;
    float pd = h0.x * d0.x + h0.y * d0.y + h0.z * d0.z + h0.w * d0.w
             + h1v.x * d1.x + h1v.y * d1.y + h1v.z * d1.z + h1v.w * d1.w;
#pragma unroll
    for (int o = 4; o; o >>= 1) {
        ps += __shfl_xor_sync(0xffffffffu, ps, o);
        pd += __shfl_xor_sync(0xffffffffu, pd, o);
    }
    if ((lane & 7) == 0) {
        int h = lane >> 3;
        g_asrc1[warp * NH + h] = ps;
        g_adst1[warp * NH + h] = pd;
    }
}

// ---------------- layer-1 aggregation: warp/node, online softmax -----------
__global__ void k_agg1(const float* __restrict__ b1, int N) {
    int node = (blockIdx.x * blockDim.x + threadIdx.x) >> 5;
    int lane = threadIdx.x & 31;
    if (node >= N) return;
    int head = lane >> 3;
    int start = g_rowptr[node], end = g_rowptr[node + 1];
    float ad = g_adst1[node * NH + head];
    float m = NEG_INF, d = 0.f;
    float acc[8];
#pragma unroll
    for (int j = 0; j < 8; j++) acc[j] = 0.f;

    for (int e = start; e < end; e++) {
        int s = g_esrc[e];
        float al = g_asrc1[s * NH + head] + ad;
        al = al > 0.f ? al : 0.2f * al;             // leaky_relu
        float mn = fmaxf(m, al);
        float sc = __expf(m - mn);                  // 0 on first edge
        float w  = __expf(al - mn);
        d = d * sc + w;
        const float4* hp = (const float4*)(g_h1 + (size_t)s * HC) + lane * 2;
        float4 v0 = hp[0], v1 = hp[1];
        acc[0] = acc[0] * sc + w * v0.x;
        acc[1] = acc[1] * sc + w * v0.y;
        acc[2] = acc[2] * sc + w * v0.z;
        acc[3] = acc[3] * sc + w * v0.w;
        acc[4] = acc[4] * sc + w * v1.x;
        acc[5] = acc[5] * sc + w * v1.y;
        acc[6] = acc[6] * sc + w * v1.z;
        acc[7] = acc[7] * sc + w * v1.w;
        m = mn;
    }
    float inv = 1.f / (d + 1e-16f);
    int col = lane * 8;
#pragma unroll
    for (int j = 0; j < 8; j++) {
        float v = acc[j] * inv + __ldg(b1 + col + j);
        acc[j] = v > 0.f ? v : (expf(v) - 1.f);     // elu
    }
    float4* op = (float4*)(g_h2 + (size_t)node * HC + col);
    op[0] = make_float4(acc[0], acc[1], acc[2], acc[3]);
    op[1] = make_float4(acc[4], acc[5], acc[6], acc[7]);
}

// ---------------- GEMM2: h3[M x 40] = h2[M x 256] @ W2[256 x 40] -----------
__global__ __launch_bounds__(256) void k_gemm2(const float* __restrict__ W2, int M) {
    __shared__ float hs[64][65];
    __shared__ float ws[64][OUTC];
    int t = threadIdx.x;
    int bm = blockIdx.x * 64;
    int cg = t & 7;
    int rg = t >> 3;
    float acc[2][5];
#pragma unroll
    for (int r = 0; r < 2; r++)
#pragma unroll
        for (int j = 0; j < 5; j++) acc[r][j] = 0.f;

    for (int kt = 0; kt < HC; kt += 64) {
#pragma unroll
        for (int i = 0; i < 4; i++) {
            int idx = t + i * 256;
            int row = idx >> 4;
            int c4  = (idx & 15) * 4;
            float4 v = make_float4(0.f, 0.f, 0.f, 0.f);
            int gr = bm + row;
            if (gr < M) v = *(const float4*)(g_h2 + (size_t)gr * HC + kt + c4);
            hs[row][c4 + 0] = v.x;
            hs[row][c4 + 1] = v.y;
            hs[row][c4 + 2] = v.z;
            hs[row][c4 + 3] = v.w;
        }
#pragma unroll
        for (int i = 0; i < 10; i++) {
            int idx = t + i * 256;
            int kr = idx / OUTC;
            int c  = idx - kr * OUTC;
            ws[kr][c] = W2[(size_t)(kt + kr) * OUTC + c];
        }
        __syncthreads();
#pragma unroll
        for (int k = 0; k < 64; k++) {
            float h0 = hs[rg * 2][k];
            float h1v = hs[rg * 2 + 1][k];
#pragma unroll
            for (int j = 0; j < 5; j++) {
                float w = ws[k][cg * 5 + j];
                acc[0][j] += h0 * w;
                acc[1][j] += h1v * w;
            }
        }
        __syncthreads();
    }
#pragma unroll
    for (int r = 0; r < 2; r++) {
        int gr = bm + rg * 2 + r;
        if (gr >= M) continue;
#pragma unroll
        for (int j = 0; j < 5; j++)
            g_h3[(size_t)gr * OUTC + cg * 5 + j] = acc[r][j];
    }
}

// ---------------- attention coefficients layer 2 ---------------------------
__global__ void k_attn2(const float* __restrict__ att_src,
                        const float* __restrict__ att_dst, int N) {
    int node = (blockIdx.x * blockDim.x + threadIdx.x) >> 5;
    int lane = threadIdx.x & 31;
    if (node >= N) return;
    const float* hp = g_h3 + (size_t)node * OUTC;
    float ps = hp[lane] * __ldg(att_src + lane);
    float pd = hp[lane] * __ldg(att_dst + lane);
    if (lane < 8) {
        ps += hp[32 + lane] * __ldg(att_src + 32 + lane);
        pd += hp[32 + lane] * __ldg(att_dst + 32 + lane);
    }
#pragma unroll
    for (int o = 16; o; o >>= 1) {
        ps += __shfl_xor_sync(0xffffffffu, ps, o);
        pd += __shfl_xor_sync(0xffffffffu, pd, o);
    }
    if (lane == 0) { g_asrc2[node] = ps; g_adst2[node] = pd; }
}

// ---------------- layer-2 aggregation + bias + log_softmax -----------------
__global__ void k_agg2(const float* __restrict__ b2, float* __restrict__ out, int N) {
    int node = (blockIdx.x * blockDim.x + threadIdx.x) >> 5;
    int lane = threadIdx.x & 31;
    if (node >= N) return;
    int start = g_rowptr[node], end = g_rowptr[node + 1];
    float ad = g_adst2[node];
    float m = NEG_INF, d = 0.f;
    float a0 = 0.f, a1 = 0.f;
    for (int e = start; e < end; e++) {
        int s = g_esrc[e];
        float al = g_asrc2[s] + ad;
        al = al > 0.f ? al : 0.2f * al;
        float mn = fmaxf(m, al);
        float sc = __expf(m - mn);
        float w  = __expf(al - mn);
        d = d * sc + w;
        const float* hp = g_h3 + (size_t)s * OUTC;
        float v0 = hp[lane];
        float v1 = (lane < 8) ? hp[32 + lane] : 0.f;
        a0 = a0 * sc + w * v0;
        a1 = a1 * sc + w * v1;
        m = mn;
    }
    float inv = 1.f / (d + 1e-16f);
    float o0 = a0 * inv + __ldg(b2 + lane);
    float o1 = (lane < 8) ? (a1 * inv + __ldg(b2 + 32 + lane)) : NEG_INF;
    float mx = fmaxf(o0, o1);
#pragma unroll
    for (int o = 16; o; o >>= 1) mx = fmaxf(mx, __shfl_xor_sync(0xffffffffu, mx, o));
    float se = expf(o0 - mx) + ((lane < 8) ? expf(o1 - mx) : 0.f);
#pragma unroll
    for (int o = 16; o; o >>= 1) se += __shfl_xor_sync(0xffffffffu, se, o);
    float L = logf(se);
    float* op = out + (size_t)node * OUTC;
    op[lane] = o0 - mx - L;
    if (lane < 8) op[32 + lane] = o1 - mx - L;
}

// ---------------- launch ----------------------------------------------------
extern "C" void kernel_launch(void* const* d_in, const int* in_sizes, int n_in,
                              void* d_out, int out_size) {
    const float* x   = (const float*)d_in[0];
    const void*  ei  = d_in[1];
    const float* W1  = (const float*)d_in[2];
    const float* as1 = (const float*)d_in[3];
    const float* ad1 = (const float*)d_in[4];
    const float* b1  = (const float*)d_in[5];
    const float* W2  = (const float*)d_in[6];
    const float* as2 = (const float*)d_in[7];
    const float* ad2 = (const float*)d_in[8];
    const float* b2  = (const float*)d_in[9];
    float*       out = (float*)d_out;

    int N = in_sizes[0] / F_IN;
    int E = in_sizes[1] / 2;

    int nb = (N + 255) / 256;
    int eb = (E + 255) / 256;
    int wb = (N + 7) / 8;   // one warp per node, 8 warps per block

    // Edge dtype normalization + CSR by destination (self loops included)
    k_detect<<<1, 32>>>(ei, E, N);
    k_init_deg<<<nb, 256>>>(N);
    k_convert_count<<<eb, 256>>>(ei, E, N);
    k_scan_a<<<SCAN_B, SCAN_T>>>(N);
    k_scan_b<<<1, SCAN_B>>>();
    k_scan_c<<<SCAN_B, SCAN_T>>>(N);
    k_scatter<<<eb, 256>>>(E);

    // Layer 1
    k_prepw<<<(F_IN * HC + 255) / 256, 256>>>(W1);
    dim3 g1((N + 127) / 128, HC / 128);
    k_gemm1_bf<<<g1, 256>>>(x, N);
    k_attn1<<<wb, 256>>>(as1, ad1, N);
    k_agg1<<<wb, 256>>>(b1, N);

    // Layer 2
    k_gemm2<<<(N + 63) / 64, 256>>>(W2, N);
    k_attn2<<<wb, 256>>>(as2, ad2, N);
    k_agg2<<<wb, 256>>>(b2, out, N);
}